// round 14
// baseline (speedup 1.0000x reference)
#include <cuda_runtime.h>
#include <cuda_bf16.h>
#include <cuda_fp16.h>
#include <cstdint>

#define NSEQ    512
#define EMB     128
#define HDIM    16
#define NBATCH  512          // B*H*C
#define M_TOTAL 32768        // B*C*N

// Scratch (__device__ globals per allocation rules)
// Q,K packed bf16 hi/lo: [g][n][w0..7 = hi pairs, w8..15 = lo pairs]; Q pre-scaled by 1/4
__device__ uint32_t g_qp[NBATCH * NSEQ * 16];
__device__ uint32_t g_kp[NBATCH * NSEQ * 16];
// V fp16 transposed: [g][d][n]
__device__ __half   g_vp[NBATCH * HDIM * NSEQ];
__device__ float    g_att[(size_t)M_TOTAL * EMB];
// Preconverted weights, frag-interleaved: [which][(n*8+ks)*4+tig] = {bh0,bh1,bl0,bl1}
__device__ uint4    g_wf[4][4096];

// ---------------------------------------------------------------------------
// mma.sync m16n8k16 (arch-unconditional HMMA)
// A frags (lane=4*gid+tig): a0=(gid,2tig) a1=(gid+8,2tig) a2=(gid,2tig+8) a3=(gid+8,2tig+8)
// B frags: b0=(k=2tig,n=gid) b1=(k=2tig+8,n=gid)
// C frags: c0=(gid,2tig) c1=(gid,2tig+1) c2=(gid+8,2tig) c3=(gid+8,2tig+1)
// ---------------------------------------------------------------------------
__device__ __forceinline__ void mma16816(float* c, const uint32_t* a, const uint32_t* b) {
    asm volatile(
        "mma.sync.aligned.m16n8k16.row.col.f32.bf16.bf16.f32 "
        "{%0,%1,%2,%3}, {%4,%5,%6,%7}, {%8,%9}, {%0,%1,%2,%3};"
        : "+f"(c[0]), "+f"(c[1]), "+f"(c[2]), "+f"(c[3])
        : "r"(a[0]), "r"(a[1]), "r"(a[2]), "r"(a[3]), "r"(b[0]), "r"(b[1]));
}
__device__ __forceinline__ void mma16816h(float* c, const uint32_t* a, const uint32_t* b) {
    asm volatile(
        "mma.sync.aligned.m16n8k16.row.col.f32.f16.f16.f32 "
        "{%0,%1,%2,%3}, {%4,%5,%6,%7}, {%8,%9}, {%0,%1,%2,%3};"
        : "+f"(c[0]), "+f"(c[1]), "+f"(c[2]), "+f"(c[3])
        : "r"(a[0]), "r"(a[1]), "r"(a[2]), "r"(a[3]), "r"(b[0]), "r"(b[1]));
}

// Split two floats into packed bf16x2 hi + lo (low 16 bits = first element)
__device__ __forceinline__ void pack_split(float p0, float p1, uint32_t& h, uint32_t& l) {
    asm("cvt.rn.bf16x2.f32 %0, %1, %2;" : "=r"(h) : "f"(p1), "f"(p0));
    float h0 = __uint_as_float(h << 16);
    float h1 = __uint_as_float(h & 0xFFFF0000u);
    float l0 = p0 - h0, l1 = p1 - h1;
    asm("cvt.rn.bf16x2.f32 %0, %1, %2;" : "=r"(l) : "f"(l1), "f"(l0));
}
__device__ __forceinline__ void split4(__nv_bfloat16* ph, __nv_bfloat16* pl, float4 v) {
    uint32_t h01, h23, l01, l23;
    pack_split(v.x, v.y, h01, l01);
    pack_split(v.z, v.w, h23, l23);
    *(uint32_t*)(ph)     = h01;
    *(uint32_t*)(ph + 2) = h23;
    *(uint32_t*)(pl)     = l01;
    *(uint32_t*)(pl + 2) = l23;
}

// ---------------------------------------------------------------------------
// One-shot weight conversion -> frag-interleaved hi/lo layout
// ---------------------------------------------------------------------------
__global__ __launch_bounds__(256) void wconv(const float* __restrict__ Wq,
                                             const float* __restrict__ Wk,
                                             const float* __restrict__ Wv,
                                             const float* __restrict__ Wout) {
    const int i     = blockIdx.x * 256 + threadIdx.x;   // 0..16383
    const int which = i >> 12;
    const int r     = i & 4095;
    const int n     = r >> 5;
    const int ks    = (r >> 2) & 7;
    const int tig   = r & 3;
    const int k0    = ks * 16 + 2 * tig;
    const float* W  = (which == 0) ? Wq : (which == 1) ? Wk : (which == 2) ? Wv : Wout;
    float2 a = *(const float2*)(W + n * EMB + k0);
    float2 b = *(const float2*)(W + n * EMB + k0 + 8);
    uint4 o;
    pack_split(a.x, a.y, o.x, o.z);
    pack_split(b.x, b.y, o.y, o.w);
    g_wf[which][r] = o;
}

// ---------------------------------------------------------------------------
// Split-bf16 GEMM tile: out[128 x 64] = X[128,128] @ W^T[:, col0:col0+64].
// 8 warps as 4(m) x 2(n): 32x32 per warp (mt=2, nt=4). acc = 32 regs ->
// ~70 regs/thread -> 3 CTAs/SM (smem 3 x 69.6KB = 209KB <= 228KB).
// X hi/lo in smem; W frags via one LDG.128 per (nt,ks).
// mode 0: fp32 [m][f]; mode 1: packed bf16 hi/lo [g][n][16w] (scaled by sc);
// mode 2: fp16 [g][d][n]
// ---------------------------------------------------------------------------
#define XS 136
#define TILE_ELEMS (128 * XS)
#define GEMM_SMEM (2 * TILE_ELEMS * 2)        // 69632 B

__device__ __forceinline__ void gemm_tile_mma(const float* __restrict__ X,
                                              const uint4* __restrict__ wf,
                                              void* __restrict__ outv,
                                              int mode, float sc, int tile, int col0,
                                              __nv_bfloat16* sm) {
    __nv_bfloat16* sXh = sm;
    __nv_bfloat16* sXl = sm + TILE_ELEMS;
    const int tid  = threadIdx.x;
    const int row0 = tile * 128;

    {
        const float4* Xv = (const float4*)(X + (size_t)row0 * EMB);
        for (int i = tid; i < 4096; i += 256) {
            const int r  = i >> 5;
            const int c4 = (i & 31) << 2;
            split4(sXh + r * XS + c4, sXl + r * XS + c4, Xv[i]);
        }
    }
    __syncthreads();

    const int lane = tid & 31;
    const int wid  = tid >> 5;
    const int gid  = lane >> 2;
    const int tig  = lane & 3;
    const int wm   = (wid & 3) * 32;    // 4 m-warps
    const int wn   = (wid >> 2) * 32;   // 2 n-warps

    float acc[2][4][4];
#pragma unroll
    for (int mt = 0; mt < 2; mt++)
#pragma unroll
        for (int nt = 0; nt < 4; nt++)
#pragma unroll
            for (int j = 0; j < 4; j++) acc[mt][nt][j] = 0.f;

#pragma unroll 1
    for (int ks = 0; ks < 8; ks++) {
        const int k0 = ks * 16 + 2 * tig;
        uint32_t bh[4][2], bl[4][2];
#pragma unroll
        for (int nt = 0; nt < 4; nt++) {
            const int n = col0 + wn + nt * 8 + gid;
            uint4 w = wf[(n * 8 + ks) * 4 + tig];
            bh[nt][0] = w.x;
            bh[nt][1] = w.y;
            bl[nt][0] = w.z;
            bl[nt][1] = w.w;
        }
#pragma unroll
        for (int mt = 0; mt < 2; mt++) {
            const int r = wm + mt * 16 + gid;
            const __nv_bfloat16* p = sXh + r * XS + k0;
            const __nv_bfloat16* q = sXl + r * XS + k0;
            uint32_t ah[4], al[4];
            ah[0] = *(const uint32_t*)p;
            ah[1] = *(const uint32_t*)(p + 8 * XS);
            ah[2] = *(const uint32_t*)(p + 8);
            ah[3] = *(const uint32_t*)(p + 8 * XS + 8);
            al[0] = *(const uint32_t*)q;
            al[1] = *(const uint32_t*)(q + 8 * XS);
            al[2] = *(const uint32_t*)(q + 8);
            al[3] = *(const uint32_t*)(q + 8 * XS + 8);
#pragma unroll
            for (int nt = 0; nt < 4; nt++) {
                mma16816(acc[mt][nt], ah, bh[nt]);
                mma16816(acc[mt][nt], al, bh[nt]);
                mma16816(acc[mt][nt], ah, bl[nt]);
            }
        }
    }

#pragma unroll
    for (int mt = 0; mt < 2; mt++) {
#pragma unroll
        for (int nt = 0; nt < 4; nt++) {
            const int f = col0 + wn + nt * 8 + 2 * tig;
#pragma unroll
            for (int half = 0; half < 2; half++) {
                const int m = row0 + wm + mt * 16 + gid + half * 8;
                float2 v = make_float2(acc[mt][nt][half * 2], acc[mt][nt][half * 2 + 1]);
                const int b = m >> 10, c = (m >> 9) & 1, n = m & 511;
                const int h = f >> 4, dd = f & 15;
                const int g = b * 16 + h * 2 + c;
                if (mode == 1) {
                    uint32_t hh, ll;
                    pack_split(v.x * sc, v.y * sc, hh, ll);
                    uint32_t* row = (uint32_t*)outv + ((size_t)(g * NSEQ + n)) * 16;
                    row[dd >> 1]       = hh;
                    row[8 + (dd >> 1)] = ll;
                } else if (mode == 2) {
                    __half* vp = (__half*)outv + (size_t)g * 8192;
                    vp[dd * 512 + n]       = __float2half_rn(v.x);
                    vp[(dd + 1) * 512 + n] = __float2half_rn(v.y);
                } else {
                    *(float2*)((float*)outv + (size_t)m * EMB + f) = v;
                }
            }
        }
    }
}

__global__ __launch_bounds__(256, 3) void proj3_mma(const float* __restrict__ Q,
                                                    const float* __restrict__ K,
                                                    const float* __restrict__ V) {
    extern __shared__ __align__(16) __nv_bfloat16 smem[];
    const int which = blockIdx.x / 512;
    const int rem   = blockIdx.x & 511;
    const int tile  = rem >> 1;
    const int col0  = (rem & 1) * 64;
    const float* X = (which == 0) ? Q : (which == 1) ? K : V;
    void* O        = (which == 0) ? (void*)g_qp : (which == 1) ? (void*)g_kp : (void*)g_vp;
    const float sc = (which == 0) ? 0.25f : 1.0f;   // fold s/4 into Q
    gemm_tile_mma(X, g_wf[which], O, (which == 2) ? 2 : 1, sc, tile, col0, smem);
}

__global__ __launch_bounds__(256, 3) void outproj_mma(const float* __restrict__ X,
                                                      float* __restrict__ out) {
    extern __shared__ __align__(16) __nv_bfloat16 smem[];
    gemm_tile_mma(X, g_wf[3], out, 0, 1.0f, blockIdx.x >> 1, (blockIdx.x & 1) * 64, smem);
}

// ---------------------------------------------------------------------------
// HMMA attention (exact R12 version — known good). grid = 1024.
// QK: split-bf16 3-mma (q pre-scaled by 1/4).
// Softmax: p = 2^(K*(tanh(s)-1)), K = 10*log2(e): 2x tanh.f32 + 1x ex2.f16x2.
// PV: fp16 mma. Denominator = P @ ones via extra fp16 mma (tig==0 lanes).
// ---------------------------------------------------------------------------
#define KW 9
#define VW 260
#define ATTN_WORDS (2 * 512 * KW + 16 * VW + 256)
#define ATTN_SMEM  (ATTN_WORDS * 4)

__global__ __launch_bounds__(256) void attn_mma(const float* __restrict__ mask) {
    extern __shared__ __align__(16) uint32_t smu[];
    uint32_t* khi = smu;
    uint32_t* klo = smu + 512 * KW;
    uint32_t* vsm = smu + 2 * 512 * KW;
    uint32_t* msm = smu + 2 * 512 * KW + 16 * VW;   // f16x2 mask pairs [256]

    const int g    = blockIdx.x >> 1;
    const int qhx  = blockIdx.x & 1;
    const int tid  = threadIdx.x;
    const int b = g >> 4, h = (g >> 1) & 7, c = g & 1;
    const int lane = tid & 31;
    const int wid  = tid >> 5;
    const int gid  = lane >> 2;
    const int tig  = lane & 3;

    // ---- copy precomputed K/V into smem ----
    {
        const uint4* kg = (const uint4*)(g_kp + (size_t)g * 8192);
        for (int i = tid; i < 2048; i += 256) {
            uint4 w = kg[i];
            const int key = i >> 2, seg = i & 3;
            uint32_t* dst = (seg < 2) ? (khi + key * KW + 4 * seg)
                                      : (klo + key * KW + 4 * (seg - 2));
            dst[0] = w.x; dst[1] = w.y; dst[2] = w.z; dst[3] = w.w;
        }
        const uint4* vg = (const uint4*)(g_vp + (size_t)g * 8192);
        for (int i = tid; i < 1024; i += 256) {
            uint4 w = vg[i];
            const int d = i >> 6, j4 = (i & 63) * 4;
            uint32_t* dst = vsm + d * VW + j4;
            dst[0] = w.x; dst[1] = w.y; dst[2] = w.z; dst[3] = w.w;
        }
        const unsigned* mrow = (const unsigned*)mask + (b * 2 + c) * NSEQ;
        for (int i = tid; i < 256; i += 256) {
            float m0 = (mrow[2 * i] != 0u) ? 0.f : 1.f;
            float m1 = (mrow[2 * i + 1] != 0u) ? 0.f : 1.f;
            __half2 mh = __floats2half2_rn(m0, m1);
            msm[i] = *(uint32_t*)&mh;
        }
    }

    // ---- Q fragments direct from packed global (pre-scaled by 1/4) ----
    uint32_t qh[2][4], ql[2][4];
    {
        const uint32_t* qg = g_qp + (size_t)g * 8192 + (size_t)(qhx * 256 + wid * 32) * 16;
#pragma unroll
        for (int mt = 0; mt < 2; mt++) {
            const uint32_t* r0 = qg + (mt * 16 + gid) * 16;
            const uint32_t* r1 = r0 + 128;
            qh[mt][0] = r0[tig];      ql[mt][0] = r0[8 + tig];
            qh[mt][1] = r1[tig];      ql[mt][1] = r1[8 + tig];
            qh[mt][2] = r0[tig + 4];  ql[mt][2] = r0[12 + tig];
            qh[mt][3] = r1[tig + 4];  ql[mt][3] = r1[12 + tig];
        }
    }
    __syncthreads();

    float oacc[2][2][4];
    float dacc[2][4];
#pragma unroll
    for (int mt = 0; mt < 2; mt++) {
#pragma unroll
        for (int j = 0; j < 4; j++) dacc[mt][j] = 0.f;
#pragma unroll
        for (int dnt = 0; dnt < 2; dnt++)
#pragma unroll
            for (int j = 0; j < 4; j++) oacc[mt][dnt][j] = 0.f;
    }

    const float KTH = 14.4269504089f;   // 10*log2(e)
    uint32_t bones[2];
    bones[0] = bones[1] = (gid == 0) ? 0x3C003C00u : 0u;      // ones col 0

#pragma unroll 1
    for (int ch = 0; ch < 16; ch++) {
        float s[2][4][4];
#pragma unroll
        for (int mt = 0; mt < 2; mt++)
#pragma unroll
            for (int nt = 0; nt < 4; nt++)
#pragma unroll
                for (int j = 0; j < 4; j++) s[mt][nt][j] = 0.f;

#pragma unroll
        for (int nt = 0; nt < 4; nt++) {
            const int key = ch * 32 + nt * 8 + gid;
            uint32_t kh[2], kl[2];
            kh[0] = khi[key * KW + tig];
            kh[1] = khi[key * KW + tig + 4];
            kl[0] = klo[key * KW + tig];
            kl[1] = klo[key * KW + tig + 4];
#pragma unroll
            for (int mt = 0; mt < 2; mt++) {
                mma16816(s[mt][nt], qh[mt], kh);
                mma16816(s[mt][nt], ql[mt], kh);
                mma16816(s[mt][nt], qh[mt], kl);
            }
        }

        // softmax: p = 2^(KTH*(tanh(s)-1)) * mask
        uint32_t pf[2][4][2];
#pragma unroll
        for (int nt = 0; nt < 4; nt++) {
            const uint32_t mword = msm[ch * 16 + nt * 4 + tig];
            const __half2 m2h = *(const __half2*)&mword;
#pragma unroll
            for (int mt = 0; mt < 2; mt++) {
#pragma unroll
                for (int pi = 0; pi < 2; pi++) {
                    float t0, t1;
                    asm("tanh.approx.f32 %0, %1;" : "=f"(t0) : "f"(s[mt][nt][pi * 2]));
                    asm("tanh.approx.f32 %0, %1;" : "=f"(t1) : "f"(s[mt][nt][pi * 2 + 1]));
                    const float y0 = fmaf(KTH, t0, -KTH);
                    const float y1 = fmaf(KTH, t1, -KTH);
                    uint32_t yw, pw;
                    asm("cvt.rn.f16x2.f32 %0, %1, %2;" : "=r"(yw) : "f"(y1), "f"(y0));
                    asm("ex2.approx.f16x2 %0, %1;" : "=r"(pw) : "r"(yw));
                    __half2 p = *(__half2*)&pw;
                    p = __hmul2(p, m2h);
                    pf[mt][nt][pi] = *(uint32_t*)&p;
                }
            }
        }

        // PV + denominator accumulate (fp16 mma)
#pragma unroll
        for (int ks = 0; ks < 2; ks++) {
            uint32_t vh[2][2];
#pragma unroll
            for (int dnt = 0; dnt < 2; dnt++) {
                const int d = dnt * 8 + gid;
                const int base = d * VW + ch * 16 + ks * 8 + tig;
                vh[dnt][0] = vsm[base];
                vh[dnt][1] = vsm[base + 4];
            }
#pragma unroll
            for (int mt = 0; mt < 2; mt++) {
                uint32_t ap[4] = {pf[mt][2 * ks][0], pf[mt][2 * ks][1],
                                  pf[mt][2 * ks + 1][0], pf[mt][2 * ks + 1][1]};
                mma16816h(oacc[mt][0], ap, vh[0]);
                mma16816h(oacc[mt][1], ap, vh[1]);
                mma16816h(dacc[mt], ap, bones);
            }
        }
    }

    // denominators live in tig==0 lanes: dacc[mt][0] = row gid, [2] = row gid+8
    float inv[2][2];
#pragma unroll
    for (int mt = 0; mt < 2; mt++) {
        float i0 = 1.f / dacc[mt][0];
        float i1 = 1.f / dacc[mt][2];
        inv[mt][0] = __shfl_sync(0xFFFFFFFFu, i0, lane & ~3);
        inv[mt][1] = __shfl_sync(0xFFFFFFFFu, i1, lane & ~3);
    }

    const int mbase = (b * 2 + c) * NSEQ;
#pragma unroll
    for (int mt = 0; mt < 2; mt++) {
        const int row = qhx * 256 + wid * 32 + mt * 16 + gid;
#pragma unroll
        for (int dnt = 0; dnt < 2; dnt++) {
            const int dcol = h * HDIM + dnt * 8 + 2 * tig;
            float* o0 = g_att + (size_t)(mbase + row) * EMB + dcol;
            float* o1 = g_att + (size_t)(mbase + row + 8) * EMB + dcol;
            *(float2*)o0 = make_float2(oacc[mt][dnt][0] * inv[mt][0],
                                       oacc[mt][dnt][1] * inv[mt][0]);
            *(float2*)o1 = make_float2(oacc[mt][dnt][2] * inv[mt][1],
                                       oacc[mt][dnt][3] * inv[mt][1]);
        }
    }
}

// ---------------------------------------------------------------------------
extern "C" void kernel_launch(void* const* d_in, const int* in_sizes, int n_in,
                              void* d_out, int out_size) {
    const float* Q    = (const float*)d_in[0];
    const float* K    = (const float*)d_in[1];
    const float* V    = (const float*)d_in[2];
    const float* mask = (const float*)d_in[3];
    const float* Wq   = (const float*)d_in[4];
    const float* Wk   = (const float*)d_in[5];
    const float* Wv   = (const float*)d_in[6];
    const float* Wout = (const float*)d_in[7];
    float* out = (float*)d_out;

    cudaFuncSetAttribute(proj3_mma,   cudaFuncAttributeMaxDynamicSharedMemorySize, GEMM_SMEM);
    cudaFuncSetAttribute(outproj_mma, cudaFuncAttributeMaxDynamicSharedMemorySize, GEMM_SMEM);
    cudaFuncSetAttribute(attn_mma,    cudaFuncAttributeMaxDynamicSharedMemorySize, ATTN_SMEM);

    float* att;
    cudaGetSymbolAddress((void**)&att, g_att);

    wconv<<<64, 256>>>(Wq, Wk, Wv, Wout);
    proj3_mma<<<1536, 256, GEMM_SMEM>>>(Q, K, V);
    attn_mma<<<1024, 256, ATTN_SMEM>>>(mask);
    outproj_mma<<<512, 256, GEMM_SMEM>>>(att, out);
}

// round 15
// speedup vs baseline: 1.1057x; 1.1057x over previous
#include <cuda_runtime.h>
#include <cuda_bf16.h>
#include <cuda_fp16.h>
#include <cstdint>

#define NSEQ    512
#define EMB     128
#define HDIM    16
#define NBATCH  512          // B*H*C
#define M_TOTAL 32768        // B*C*N

// Scratch (__device__ globals per allocation rules)
// Q,K packed bf16 hi/lo: [g][n][w0..7 = hi pairs, w8..15 = lo pairs]; Q pre-scaled by 1/4
__device__ uint32_t g_qp[NBATCH * NSEQ * 16];
__device__ uint32_t g_kp[NBATCH * NSEQ * 16];
// V fp16 transposed: [g][d][n]
__device__ __half   g_vp[NBATCH * HDIM * NSEQ];
__device__ float    g_att[(size_t)M_TOTAL * EMB];
// Preconverted weights, frag-interleaved: [which][(n*8+ks)*4+tig] = {bh0,bh1,bl0,bl1}
__device__ uint4    g_wf[4][4096];

// ---------------------------------------------------------------------------
// mma.sync m16n8k16 (arch-unconditional HMMA)
// A frags (lane=4*gid+tig): a0=(gid,2tig) a1=(gid+8,2tig) a2=(gid,2tig+8) a3=(gid+8,2tig+8)
// B frags: b0=(k=2tig,n=gid) b1=(k=2tig+8,n=gid)
// C frags: c0=(gid,2tig) c1=(gid,2tig+1) c2=(gid+8,2tig) c3=(gid+8,2tig+1)
// ---------------------------------------------------------------------------
__device__ __forceinline__ void mma16816(float* c, const uint32_t* a, const uint32_t* b) {
    asm volatile(
        "mma.sync.aligned.m16n8k16.row.col.f32.bf16.bf16.f32 "
        "{%0,%1,%2,%3}, {%4,%5,%6,%7}, {%8,%9}, {%0,%1,%2,%3};"
        : "+f"(c[0]), "+f"(c[1]), "+f"(c[2]), "+f"(c[3])
        : "r"(a[0]), "r"(a[1]), "r"(a[2]), "r"(a[3]), "r"(b[0]), "r"(b[1]));
}
__device__ __forceinline__ void mma16816h(float* c, const uint32_t* a, const uint32_t* b) {
    asm volatile(
        "mma.sync.aligned.m16n8k16.row.col.f32.f16.f16.f32 "
        "{%0,%1,%2,%3}, {%4,%5,%6,%7}, {%8,%9}, {%0,%1,%2,%3};"
        : "+f"(c[0]), "+f"(c[1]), "+f"(c[2]), "+f"(c[3])
        : "r"(a[0]), "r"(a[1]), "r"(a[2]), "r"(a[3]), "r"(b[0]), "r"(b[1]));
}

// Split two floats into packed bf16x2 hi + lo (low 16 bits = first element)
__device__ __forceinline__ void pack_split(float p0, float p1, uint32_t& h, uint32_t& l) {
    asm("cvt.rn.bf16x2.f32 %0, %1, %2;" : "=r"(h) : "f"(p1), "f"(p0));
    float h0 = __uint_as_float(h << 16);
    float h1 = __uint_as_float(h & 0xFFFF0000u);
    float l0 = p0 - h0, l1 = p1 - h1;
    asm("cvt.rn.bf16x2.f32 %0, %1, %2;" : "=r"(l) : "f"(l1), "f"(l0));
}
__device__ __forceinline__ void split4(__nv_bfloat16* ph, __nv_bfloat16* pl, float4 v) {
    uint32_t h01, h23, l01, l23;
    pack_split(v.x, v.y, h01, l01);
    pack_split(v.z, v.w, h23, l23);
    *(uint32_t*)(ph)     = h01;
    *(uint32_t*)(ph + 2) = h23;
    *(uint32_t*)(pl)     = l01;
    *(uint32_t*)(pl + 2) = l23;
}

// ---------------------------------------------------------------------------
// One-shot weight conversion -> frag-interleaved hi/lo layout
// ---------------------------------------------------------------------------
__global__ __launch_bounds__(256) void wconv(const float* __restrict__ Wq,
                                             const float* __restrict__ Wk,
                                             const float* __restrict__ Wv,
                                             const float* __restrict__ Wout) {
    const int i     = blockIdx.x * 256 + threadIdx.x;   // 0..16383
    const int which = i >> 12;
    const int r     = i & 4095;
    const int n     = r >> 5;
    const int ks    = (r >> 2) & 7;
    const int tig   = r & 3;
    const int k0    = ks * 16 + 2 * tig;
    const float* W  = (which == 0) ? Wq : (which == 1) ? Wk : (which == 2) ? Wv : Wout;
    float2 a = *(const float2*)(W + n * EMB + k0);
    float2 b = *(const float2*)(W + n * EMB + k0 + 8);
    uint4 o;
    pack_split(a.x, a.y, o.x, o.z);
    pack_split(b.x, b.y, o.y, o.w);
    g_wf[which][r] = o;
}

// ---------------------------------------------------------------------------
// Split-bf16 GEMM tile (EXACT R12 config): out[128 x 128] = X[128,128] @ W^T.
// X hi/lo in smem (69.6KB, 2 CTAs/SM); W frags via one LDG.128 per (nt,ks).
// mode 0: fp32 [m][f]; mode 1: packed bf16 hi/lo [g][n][16w] (scaled by sc);
// mode 2: fp16 [g][d][n]
// ---------------------------------------------------------------------------
#define XS 136
#define TILE_ELEMS (128 * XS)
#define GEMM_SMEM (2 * TILE_ELEMS * 2)        // 69632 B

__device__ __forceinline__ void gemm_tile_mma(const float* __restrict__ X,
                                              const uint4* __restrict__ wf,
                                              void* __restrict__ outv,
                                              int mode, float sc, int tile,
                                              __nv_bfloat16* sm) {
    __nv_bfloat16* sXh = sm;
    __nv_bfloat16* sXl = sm + TILE_ELEMS;
    const int tid  = threadIdx.x;
    const int row0 = tile * 128;

    {
        const float4* Xv = (const float4*)(X + (size_t)row0 * EMB);
        for (int i = tid; i < 4096; i += 256) {
            const int r  = i >> 5;
            const int c4 = (i & 31) << 2;
            split4(sXh + r * XS + c4, sXl + r * XS + c4, Xv[i]);
        }
    }
    __syncthreads();

    const int lane = tid & 31;
    const int wid  = tid >> 5;
    const int gid  = lane >> 2;
    const int tig  = lane & 3;
    const int wm   = (wid & 1) * 64;
    const int wn   = (wid >> 1) * 32;

    float acc[4][4][4];
#pragma unroll
    for (int mt = 0; mt < 4; mt++)
#pragma unroll
        for (int nt = 0; nt < 4; nt++)
#pragma unroll
            for (int j = 0; j < 4; j++) acc[mt][nt][j] = 0.f;

#pragma unroll 1
    for (int ks = 0; ks < 8; ks++) {
        const int k0 = ks * 16 + 2 * tig;
        uint32_t bh[4][2], bl[4][2];
#pragma unroll
        for (int nt = 0; nt < 4; nt++) {
            const int n = wn + nt * 8 + gid;
            uint4 w = wf[(n * 8 + ks) * 4 + tig];
            bh[nt][0] = w.x;
            bh[nt][1] = w.y;
            bl[nt][0] = w.z;
            bl[nt][1] = w.w;
        }
#pragma unroll
        for (int mt = 0; mt < 4; mt++) {
            const int r = wm + mt * 16 + gid;
            const __nv_bfloat16* p = sXh + r * XS + k0;
            const __nv_bfloat16* q = sXl + r * XS + k0;
            uint32_t ah[4], al[4];
            ah[0] = *(const uint32_t*)p;
            ah[1] = *(const uint32_t*)(p + 8 * XS);
            ah[2] = *(const uint32_t*)(p + 8);
            ah[3] = *(const uint32_t*)(p + 8 * XS + 8);
            al[0] = *(const uint32_t*)q;
            al[1] = *(const uint32_t*)(q + 8 * XS);
            al[2] = *(const uint32_t*)(q + 8);
            al[3] = *(const uint32_t*)(q + 8 * XS + 8);
#pragma unroll
            for (int nt = 0; nt < 4; nt++) {
                mma16816(acc[mt][nt], ah, bh[nt]);
                mma16816(acc[mt][nt], al, bh[nt]);
                mma16816(acc[mt][nt], ah, bl[nt]);
            }
        }
    }

#pragma unroll
    for (int mt = 0; mt < 4; mt++) {
#pragma unroll
        for (int nt = 0; nt < 4; nt++) {
            const int f = wn + nt * 8 + 2 * tig;
#pragma unroll
            for (int half = 0; half < 2; half++) {
                const int m = row0 + wm + mt * 16 + gid + half * 8;
                float2 v = make_float2(acc[mt][nt][half * 2], acc[mt][nt][half * 2 + 1]);
                const int b = m >> 10, c = (m >> 9) & 1, n = m & 511;
                const int h = f >> 4, dd = f & 15;
                const int g = b * 16 + h * 2 + c;
                if (mode == 1) {
                    uint32_t hh, ll;
                    pack_split(v.x * sc, v.y * sc, hh, ll);
                    uint32_t* row = (uint32_t*)outv + ((size_t)(g * NSEQ + n)) * 16;
                    row[dd >> 1]       = hh;
                    row[8 + (dd >> 1)] = ll;
                } else if (mode == 2) {
                    __half* vp = (__half*)outv + (size_t)g * 8192;
                    vp[dd * 512 + n]       = __float2half_rn(v.x);
                    vp[(dd + 1) * 512 + n] = __float2half_rn(v.y);
                } else {
                    *(float2*)((float*)outv + (size_t)m * EMB + f) = v;
                }
            }
        }
    }
}

__global__ __launch_bounds__(256) void proj3_mma(const float* __restrict__ Q,
                                                 const float* __restrict__ K,
                                                 const float* __restrict__ V) {
    extern __shared__ __align__(16) __nv_bfloat16 smem[];
    const int which = blockIdx.x >> 8;
    const int tile  = blockIdx.x & 255;
    const float* X = (which == 0) ? Q : (which == 1) ? K : V;
    void* O        = (which == 0) ? (void*)g_qp : (which == 1) ? (void*)g_kp : (void*)g_vp;
    const float sc = (which == 0) ? 0.25f : 1.0f;   // fold s/4 into Q
    gemm_tile_mma(X, g_wf[which], O, (which == 2) ? 2 : 1, sc, tile, smem);
}

__global__ __launch_bounds__(256) void outproj_mma(const float* __restrict__ X,
                                                   float* __restrict__ out) {
    extern __shared__ __align__(16) __nv_bfloat16 smem[];
    gemm_tile_mma(X, g_wf[3], out, 0, 1.0f, blockIdx.x, smem);
}

// ---------------------------------------------------------------------------
// HMMA attention. grid = 1024: block = (g, qhalf); 8 warps x 32 q-rows.
// Restructured for low registers + 3 CTAs/SM: keys processed in 16-wide
// sub-chunks; per 8-key group QK-mma -> softmax immediately (live s = 8 regs,
// pf = 8 regs), then PV + denominator right away.
// QK: split-bf16 3-mma (q pre-scaled by 1/4).
// Softmax: p = 2^(K*(tanh(s)-1)), K = 10*log2(e): 2x tanh.f32 + 1x ex2.f16x2.
// PV: fp16 mma. Denominator = P @ ones via extra fp16 mma (tig==0 lanes).
// ---------------------------------------------------------------------------
#define KW 9
#define VW 260
#define ATTN_WORDS (2 * 512 * KW + 16 * VW + 256)
#define ATTN_SMEM  (ATTN_WORDS * 4)

__global__ __launch_bounds__(256, 3) void attn_mma(const float* __restrict__ mask) {
    extern __shared__ __align__(16) uint32_t smu[];
    uint32_t* khi = smu;
    uint32_t* klo = smu + 512 * KW;
    uint32_t* vsm = smu + 2 * 512 * KW;
    uint32_t* msm = smu + 2 * 512 * KW + 16 * VW;   // f16x2 mask pairs [256]

    const int g    = blockIdx.x >> 1;
    const int qhx  = blockIdx.x & 1;
    const int tid  = threadIdx.x;
    const int b = g >> 4, h = (g >> 1) & 7, c = g & 1;
    const int lane = tid & 31;
    const int wid  = tid >> 5;
    const int gid  = lane >> 2;
    const int tig  = lane & 3;

    // ---- copy precomputed K/V into smem ----
    {
        const uint4* kg = (const uint4*)(g_kp + (size_t)g * 8192);
        for (int i = tid; i < 2048; i += 256) {
            uint4 w = kg[i];
            const int key = i >> 2, seg = i & 3;
            uint32_t* dst = (seg < 2) ? (khi + key * KW + 4 * seg)
                                      : (klo + key * KW + 4 * (seg - 2));
            dst[0] = w.x; dst[1] = w.y; dst[2] = w.z; dst[3] = w.w;
        }
        const uint4* vg = (const uint4*)(g_vp + (size_t)g * 8192);
        for (int i = tid; i < 1024; i += 256) {
            uint4 w = vg[i];
            const int d = i >> 6, j4 = (i & 63) * 4;
            uint32_t* dst = vsm + d * VW + j4;
            dst[0] = w.x; dst[1] = w.y; dst[2] = w.z; dst[3] = w.w;
        }
        const unsigned* mrow = (const unsigned*)mask + (b * 2 + c) * NSEQ;
        for (int i = tid; i < 256; i += 256) {
            float m0 = (mrow[2 * i] != 0u) ? 0.f : 1.f;
            float m1 = (mrow[2 * i + 1] != 0u) ? 0.f : 1.f;
            __half2 mh = __floats2half2_rn(m0, m1);
            msm[i] = *(uint32_t*)&mh;
        }
    }

    // ---- Q fragments direct from packed global (pre-scaled by 1/4) ----
    uint32_t qh[2][4], ql[2][4];
    {
        const uint32_t* qg = g_qp + (size_t)g * 8192 + (size_t)(qhx * 256 + wid * 32) * 16;
#pragma unroll
        for (int mt = 0; mt < 2; mt++) {
            const uint32_t* r0 = qg + (mt * 16 + gid) * 16;
            const uint32_t* r1 = r0 + 128;
            qh[mt][0] = r0[tig];      ql[mt][0] = r0[8 + tig];
            qh[mt][1] = r1[tig];      ql[mt][1] = r1[8 + tig];
            qh[mt][2] = r0[tig + 4];  ql[mt][2] = r0[12 + tig];
            qh[mt][3] = r1[tig + 4];  ql[mt][3] = r1[12 + tig];
        }
    }
    __syncthreads();

    float oacc[2][2][4];
    float dacc[2][4];
#pragma unroll
    for (int mt = 0; mt < 2; mt++) {
#pragma unroll
        for (int j = 0; j < 4; j++) dacc[mt][j] = 0.f;
#pragma unroll
        for (int dnt = 0; dnt < 2; dnt++)
#pragma unroll
            for (int j = 0; j < 4; j++) oacc[mt][dnt][j] = 0.f;
    }

    const float KTH = 14.4269504089f;   // 10*log2(e)
    uint32_t bones[2];
    bones[0] = bones[1] = (gid == 0) ? 0x3C003C00u : 0u;      // ones col 0

#pragma unroll 1
    for (int ch = 0; ch < 16; ch++) {
#pragma unroll
        for (int ks = 0; ks < 2; ks++) {
            // P fragments for this 16-key sub-chunk (2 x 8-key groups)
            uint32_t pf[2][2][2];
#pragma unroll
            for (int nt2 = 0; nt2 < 2; nt2++) {
                const int nt  = ks * 2 + nt2;
                const int key = ch * 32 + nt * 8 + gid;
                uint32_t kh[2], kl[2];
                kh[0] = khi[key * KW + tig];
                kh[1] = khi[key * KW + tig + 4];
                kl[0] = klo[key * KW + tig];
                kl[1] = klo[key * KW + tig + 4];
                float s[2][4];
#pragma unroll
                for (int mt = 0; mt < 2; mt++) {
#pragma unroll
                    for (int j = 0; j < 4; j++) s[mt][j] = 0.f;
                    mma16816(s[mt], qh[mt], kh);
                    mma16816(s[mt], ql[mt], kh);
                    mma16816(s[mt], qh[mt], kl);
                }
                // softmax: p = 2^(KTH*(tanh(s)-1)) * mask
                const uint32_t mword = msm[ch * 16 + nt * 4 + tig];
                const __half2 m2h = *(const __half2*)&mword;
#pragma unroll
                for (int mt = 0; mt < 2; mt++) {
#pragma unroll
                    for (int pi = 0; pi < 2; pi++) {
                        float t0, t1;
                        asm("tanh.approx.f32 %0, %1;" : "=f"(t0) : "f"(s[mt][pi * 2]));
                        asm("tanh.approx.f32 %0, %1;" : "=f"(t1) : "f"(s[mt][pi * 2 + 1]));
                        const float y0 = fmaf(KTH, t0, -KTH);
                        const float y1 = fmaf(KTH, t1, -KTH);
                        uint32_t yw, pw;
                        asm("cvt.rn.f16x2.f32 %0, %1, %2;" : "=r"(yw) : "f"(y1), "f"(y0));
                        asm("ex2.approx.f16x2 %0, %1;" : "=r"(pw) : "r"(yw));
                        __half2 p = *(__half2*)&pw;
                        p = __hmul2(p, m2h);
                        pf[mt][nt2][pi] = *(uint32_t*)&p;
                    }
                }
            }

            // PV + denominator for this 16-key sub-chunk (fp16 mma)
            uint32_t vh[2][2];
#pragma unroll
            for (int dnt = 0; dnt < 2; dnt++) {
                const int d = dnt * 8 + gid;
                const int base = d * VW + ch * 16 + ks * 8 + tig;
                vh[dnt][0] = vsm[base];
                vh[dnt][1] = vsm[base + 4];
            }
#pragma unroll
            for (int mt = 0; mt < 2; mt++) {
                uint32_t ap[4] = {pf[mt][0][0], pf[mt][0][1],
                                  pf[mt][1][0], pf[mt][1][1]};
                mma16816h(oacc[mt][0], ap, vh[0]);
                mma16816h(oacc[mt][1], ap, vh[1]);
                mma16816h(dacc[mt], ap, bones);
            }
        }
    }

    // denominators live in tig==0 lanes: dacc[mt][0] = row gid, [2] = row gid+8
    float inv[2][2];
#pragma unroll
    for (int mt = 0; mt < 2; mt++) {
        float i0 = 1.f / dacc[mt][0];
        float i1 = 1.f / dacc[mt][2];
        inv[mt][0] = __shfl_sync(0xFFFFFFFFu, i0, lane & ~3);
        inv[mt][1] = __shfl_sync(0xFFFFFFFFu, i1, lane & ~3);
    }

    const int mbase = (b * 2 + c) * NSEQ;
#pragma unroll
    for (int mt = 0; mt < 2; mt++) {
        const int row = qhx * 256 + wid * 32 + mt * 16 + gid;
#pragma unroll
        for (int dnt = 0; dnt < 2; dnt++) {
            const int dcol = h * HDIM + dnt * 8 + 2 * tig;
            float* o0 = g_att + (size_t)(mbase + row) * EMB + dcol;
            float* o1 = g_att + (size_t)(mbase + row + 8) * EMB + dcol;
            *(float2*)o0 = make_float2(oacc[mt][dnt][0] * inv[mt][0],
                                       oacc[mt][dnt][1] * inv[mt][0]);
            *(float2*)o1 = make_float2(oacc[mt][dnt][2] * inv[mt][1],
                                       oacc[mt][dnt][3] * inv[mt][1]);
        }
    }
}

// ---------------------------------------------------------------------------
extern "C" void kernel_launch(void* const* d_in, const int* in_sizes, int n_in,
                              void* d_out, int out_size) {
    const float* Q    = (const float*)d_in[0];
    const float* K    = (const float*)d_in[1];
    const float* V    = (const float*)d_in[2];
    const float* mask = (const float*)d_in[3];
    const float* Wq   = (const float*)d_in[4];
    const float* Wk   = (const float*)d_in[5];
    const float* Wv   = (const float*)d_in[6];
    const float* Wout = (const float*)d_in[7];
    float* out = (float*)d_out;

    cudaFuncSetAttribute(proj3_mma,   cudaFuncAttributeMaxDynamicSharedMemorySize, GEMM_SMEM);
    cudaFuncSetAttribute(outproj_mma, cudaFuncAttributeMaxDynamicSharedMemorySize, GEMM_SMEM);
    cudaFuncSetAttribute(attn_mma,    cudaFuncAttributeMaxDynamicSharedMemorySize, ATTN_SMEM);

    float* att;
    cudaGetSymbolAddress((void**)&att, g_att);

    wconv<<<64, 256>>>(Wq, Wk, Wv, Wout);
    proj3_mma<<<768, 256, GEMM_SMEM>>>(Q, K, V);
    attn_mma<<<1024, 256, ATTN_SMEM>>>(mask);
    outproj_mma<<<256, 256, GEMM_SMEM>>>(att, out);
}